// round 1
// baseline (speedup 1.0000x reference)
#include <cuda_runtime.h>
#include <math.h>

#define BB 128
#define TT 512
#define IND 64
#define HD 256
#define G3 768
#define LD 32
#define NPARD 1056
#define ODD 8

// Scratch (static device arrays — no allocation allowed)
__device__ float g_gx[BB*TT*G3];    // 192 MB
__device__ float g_rnn[BB*TT*HD];   // 64 MB
__device__ float g_te[BB*TT*LD];    // 8 MB

__device__ __forceinline__ float sigm(float x){ return 1.0f/(1.0f+expf(-x)); }

// ------------------------------------------------------------------
// K1: gx[bt,g] = x[bt,:] . w_ih[g,:] + b_ih[g]
// 64x64 tile, K=64 (whole), block 16x16 threads, 4x4 microtile
// ------------------------------------------------------------------
__global__ __launch_bounds__(256) void k_gx(const float* __restrict__ x,
                                            const float* __restrict__ w_ih,
                                            const float* __restrict__ b_ih)
{
    __shared__ float xs[64][65];
    __shared__ float ws[64][65];
    int m0 = blockIdx.y * 64;
    int n0 = blockIdx.x * 64;
    int tid = threadIdx.y * 16 + threadIdx.x;
    const float4* x4 = (const float4*)x;
    const float4* w4 = (const float4*)w_ih;
    for (int q = tid; q < 1024; q += 256) {
        int row = q >> 4, c4 = q & 15;
        float4 v = x4[(size_t)(m0 + row) * 16 + c4];
        xs[row][c4*4+0] = v.x; xs[row][c4*4+1] = v.y;
        xs[row][c4*4+2] = v.z; xs[row][c4*4+3] = v.w;
        float4 wv = w4[(size_t)(n0 + row) * 16 + c4];
        ws[row][c4*4+0] = wv.x; ws[row][c4*4+1] = wv.y;
        ws[row][c4*4+2] = wv.z; ws[row][c4*4+3] = wv.w;
    }
    __syncthreads();
    int tr = threadIdx.y * 4, tc = threadIdx.x * 4;
    float acc[4][4] = {};
    #pragma unroll 8
    for (int k = 0; k < 64; k++) {
        float av[4], bv[4];
        #pragma unroll
        for (int i = 0; i < 4; i++) av[i] = xs[tr + i][k];
        #pragma unroll
        for (int j = 0; j < 4; j++) bv[j] = ws[tc + j][k];
        #pragma unroll
        for (int i = 0; i < 4; i++)
            #pragma unroll
            for (int j = 0; j < 4; j++)
                acc[i][j] = fmaf(av[i], bv[j], acc[i][j]);
    }
    float b0 = b_ih[n0+tc+0], b1 = b_ih[n0+tc+1], b2 = b_ih[n0+tc+2], b3 = b_ih[n0+tc+3];
    #pragma unroll
    for (int i = 0; i < 4; i++) {
        float4 o;
        o.x = acc[i][0] + b0; o.y = acc[i][1] + b1;
        o.z = acc[i][2] + b2; o.w = acc[i][3] + b3;
        *(float4*)&g_gx[(size_t)(m0 + tr + i) * G3 + n0 + tc] = o;
    }
}

// ------------------------------------------------------------------
// K2: GRU recurrence. 64 blocks x 2 batch each, 768 threads.
// Thread r owns gate-row r (accumulates 2 batches); threads<512 do gates.
// ------------------------------------------------------------------
__global__ __launch_bounds__(768) void k_gru(const float* __restrict__ hidden,
                                             const float* __restrict__ w_hh,
                                             const float* __restrict__ b_hh,
                                             float* __restrict__ hT)
{
    __shared__ float4 hs4[2][64];      // current hidden, 2 batches x 256
    __shared__ float  ghs[2][G3];      // gh partials
    float* hs = (float*)hs4;
    int tid = threadIdx.x;
    int b0 = blockIdx.x * 2;

    if (tid < 512) { int b = tid >> 8, j = tid & 255; hs[b*HD + j] = hidden[(size_t)(b0+b)*HD + j]; }
    float bh = b_hh[tid];
    const float4* w4 = (const float4*)w_hh + (size_t)tid * 64;
    __syncthreads();

    for (int t = 0; t < TT; t++) {
        // prefetch gx for the gate phase (independent of row phase)
        float xr = 0.f, xz = 0.f, xn = 0.f;
        int bt = 0;
        if (tid < 512) {
            int b = tid >> 8, j = tid & 255;
            bt = (b0 + b) * TT + t;
            const float* gxp = g_gx + (size_t)bt * G3;
            xr = gxp[j]; xz = gxp[HD + j]; xn = gxp[2*HD + j];
        }
        // row phase: gh[row] for both batches
        float a0 = bh, a1 = bh;
        #pragma unroll 8
        for (int k4 = 0; k4 < 64; k4++) {
            float4 w  = w4[k4];
            float4 h0 = hs4[0][k4];
            float4 h1 = hs4[1][k4];
            a0 = fmaf(w.x, h0.x, a0); a0 = fmaf(w.y, h0.y, a0);
            a0 = fmaf(w.z, h0.z, a0); a0 = fmaf(w.w, h0.w, a0);
            a1 = fmaf(w.x, h1.x, a1); a1 = fmaf(w.y, h1.y, a1);
            a1 = fmaf(w.z, h1.z, a1); a1 = fmaf(w.w, h1.w, a1);
        }
        ghs[0][tid] = a0;
        ghs[1][tid] = a1;
        __syncthreads();
        // gate phase
        if (tid < 512) {
            int b = tid >> 8, j = tid & 255;
            float hr = ghs[b][j], hz = ghs[b][HD + j], hn = ghs[b][2*HD + j];
            float r = sigm(xr + hr);
            float z = sigm(xz + hz);
            float n = tanhf(xn + r * hn);
            float hp = hs[b*HD + j];
            float hnew = (1.0f - z) * n + z * hp;
            hs[b*HD + j] = hnew;
            g_rnn[(size_t)bt * HD + j] = hnew;
        }
        __syncthreads();
    }
    if (tid < 512) { int b = tid >> 8, j = tid & 255; hT[(size_t)(b0+b)*HD + j] = hs[b*HD + j]; }
}

// ------------------------------------------------------------------
// K3a: task_enc[bt,l] = rnn[bt,:] . w_lat[l,:] + b_lat[l]
// 32 pairs/block, 256 threads: thread = (pair, group-of-4 outputs)
// ------------------------------------------------------------------
__global__ __launch_bounds__(256) void k_te(const float* __restrict__ w_lat,
                                            const float* __restrict__ b_lat)
{
    __shared__ float4 rows4[32 * 64];
    int tid = threadIdx.x;
    int bt0 = blockIdx.x * 32;
    const float4* rnn4 = (const float4*)g_rnn;
    for (int q = tid; q < 2048; q += 256) rows4[q] = rnn4[(size_t)bt0 * 64 + q];
    __syncthreads();
    int pair = tid >> 3;
    int l0 = (tid & 7) * 4;
    const float4* wl4 = (const float4*)w_lat;
    float acc[4];
    #pragma unroll
    for (int j = 0; j < 4; j++) acc[j] = b_lat[l0 + j];
    #pragma unroll 8
    for (int k4 = 0; k4 < 64; k4++) {
        float4 r = rows4[pair * 64 + k4];
        #pragma unroll
        for (int j = 0; j < 4; j++) {
            float4 w = wl4[(size_t)(l0 + j) * 64 + k4];
            acc[j] = fmaf(r.x, w.x, acc[j]);
            acc[j] = fmaf(r.y, w.y, acc[j]);
            acc[j] = fmaf(r.z, w.z, acc[j]);
            acc[j] = fmaf(r.w, w.w, acc[j]);
        }
    }
    float4 o = {acc[0], acc[1], acc[2], acc[3]};
    *(float4*)&g_te[(size_t)(bt0 + pair) * LD + l0] = o;
}

// ------------------------------------------------------------------
// K3b: fused params GEMM (K=32) + hyper-MLP + outputs. 8 pairs/block.
// ------------------------------------------------------------------
#define PAIRS 8
__global__ __launch_bounds__(256) void k_tail(const float* __restrict__ x,
                                              const float* __restrict__ w_par,
                                              const float* __restrict__ b_par,
                                              float* __restrict__ out_mean,
                                              float* __restrict__ out_std)
{
    __shared__ float te_s[PAIRS][33];
    __shared__ float st_s[PAIRS][49];
    __shared__ float ps[PAIRS * NPARD];
    __shared__ float hid[PAIRS][17];
    int tid = threadIdx.x;
    int bt0 = blockIdx.x * PAIRS;

    if (tid < PAIRS * 32) { int p = tid >> 5, l = tid & 31; te_s[p][l] = g_te[(size_t)(bt0 + p) * LD + l]; }
    for (int q = tid; q < PAIRS * 48; q += 256) {
        int p = q / 48, i = q % 48;
        st_s[p][i] = x[(size_t)(bt0 + p) * IND + i];
    }
    __syncthreads();

    // params[pair][idx] = b_par[idx] + sum_l w_par[idx][l]*te[pair][l]
    for (int idx = tid; idx < NPARD; idx += 256) {
        float wreg[32];
        const float4* wp4 = (const float4*)w_par + (size_t)idx * 8;
        #pragma unroll
        for (int q = 0; q < 8; q++) {
            float4 v = wp4[q];
            wreg[q*4+0] = v.x; wreg[q*4+1] = v.y; wreg[q*4+2] = v.z; wreg[q*4+3] = v.w;
        }
        float bp = b_par[idx];
        float accs[PAIRS];
        #pragma unroll
        for (int p = 0; p < PAIRS; p++) accs[p] = bp;
        #pragma unroll
        for (int l = 0; l < 32; l++) {
            float w = wreg[l];
            #pragma unroll
            for (int p = 0; p < PAIRS; p++) accs[p] = fmaf(w, te_s[p][l], accs[p]);
        }
        #pragma unroll
        for (int p = 0; p < PAIRS; p++) ps[p * NPARD + idx] = accs[p];
    }
    __syncthreads();

    // out_hidden[pair][p] = tanh( sum_i w_h[p][i]*state[i] + b_h[p] )
    if (tid < PAIRS * 16) {
        int pair = tid >> 4, p = tid & 15;
        const float* pp = ps + pair * NPARD;
        float a = pp[768 + p];
        #pragma unroll
        for (int i = 0; i < 48; i++) a = fmaf(pp[p * 48 + i], st_s[pair][i], a);
        hid[pair][p] = tanhf(a);
    }
    __syncthreads();

    // mlp[pair][o] = sum_p w_o[o][p]*hidden[p] + b_o[o]; mean / exp(std)
    if (tid < PAIRS * 16) {
        int pair = tid >> 4, o = tid & 15;
        const float* pp = ps + pair * NPARD;
        float m = pp[1040 + o];
        #pragma unroll
        for (int p = 0; p < 16; p++) m = fmaf(pp[784 + o * 16 + p], hid[pair][p], m);
        size_t bt = bt0 + pair;
        if (o < 8) out_mean[bt * ODD + o] = m;
        else       out_std[bt * ODD + (o - 8)] = expf(m);
    }
}

// ------------------------------------------------------------------
extern "C" void kernel_launch(void* const* d_in, const int* in_sizes, int n_in,
                              void* d_out, int out_size)
{
    const float* x      = (const float*)d_in[0];
    const float* hidden = (const float*)d_in[1];
    const float* w_ih   = (const float*)d_in[2];
    const float* w_hh   = (const float*)d_in[3];
    const float* b_ih   = (const float*)d_in[4];
    const float* b_hh   = (const float*)d_in[5];
    const float* w_lat  = (const float*)d_in[6];
    const float* b_lat  = (const float*)d_in[7];
    const float* w_par  = (const float*)d_in[8];
    const float* b_par  = (const float*)d_in[9];
    (void)in_sizes; (void)n_in; (void)out_size;

    float* out      = (float*)d_out;
    float* out_mean = out;                                  // B*T*8
    float* out_std  = out + (size_t)BB * TT * ODD;          // B*T*8
    float* out_hT   = out + (size_t)2 * BB * TT * ODD;      // B*256

    dim3 g1(G3 / 64, (BB * TT) / 64), b1(16, 16);
    k_gx  <<<g1, b1>>>(x, w_ih, b_ih);
    k_gru <<<BB / 2, 768>>>(hidden, w_hh, b_hh, out_hT);
    k_te  <<<(BB * TT) / 32, 256>>>(w_lat, b_lat);
    k_tail<<<(BB * TT) / PAIRS, 256>>>(x, w_par, b_par, out_mean, out_std);
}

// round 2
// speedup vs baseline: 5.2368x; 5.2368x over previous
#include <cuda_runtime.h>
#include <math.h>

#define BB 128
#define TT 512
#define IND 64
#define HD 256
#define G3 768
#define LD 32
#define NPARD 1056
#define ODD 8

#define CL 4            // cluster size (K split of hidden dim)
#define NBAT 4          // batches per cluster
#define KS (HD/CL)      // 64 K-columns per CTA

// Scratch (static device arrays — no allocation allowed)
__device__ float g_gx[BB*TT*G3];    // 192 MB
__device__ float g_rnn[BB*TT*HD];   // 64 MB
__device__ float g_te[BB*TT*LD];    // 8 MB

__device__ __forceinline__ float sigm(float x){ return 1.0f/(1.0f+expf(-x)); }

// ------------------------------------------------------------------
// K1: gx[bt,g] = x[bt,:] . w_ih[g,:] + b_ih[g]
// ------------------------------------------------------------------
__global__ __launch_bounds__(256) void k_gx(const float* __restrict__ x,
                                            const float* __restrict__ w_ih,
                                            const float* __restrict__ b_ih)
{
    __shared__ float xs[64][65];
    __shared__ float ws[64][65];
    int m0 = blockIdx.y * 64;
    int n0 = blockIdx.x * 64;
    int tid = threadIdx.y * 16 + threadIdx.x;
    const float4* x4 = (const float4*)x;
    const float4* w4 = (const float4*)w_ih;
    for (int q = tid; q < 1024; q += 256) {
        int row = q >> 4, c4 = q & 15;
        float4 v = x4[(size_t)(m0 + row) * 16 + c4];
        xs[row][c4*4+0] = v.x; xs[row][c4*4+1] = v.y;
        xs[row][c4*4+2] = v.z; xs[row][c4*4+3] = v.w;
        float4 wv = w4[(size_t)(n0 + row) * 16 + c4];
        ws[row][c4*4+0] = wv.x; ws[row][c4*4+1] = wv.y;
        ws[row][c4*4+2] = wv.z; ws[row][c4*4+3] = wv.w;
    }
    __syncthreads();
    int tr = threadIdx.y * 4, tc = threadIdx.x * 4;
    float acc[4][4] = {};
    #pragma unroll 8
    for (int k = 0; k < 64; k++) {
        float av[4], bv[4];
        #pragma unroll
        for (int i = 0; i < 4; i++) av[i] = xs[tr + i][k];
        #pragma unroll
        for (int j = 0; j < 4; j++) bv[j] = ws[tc + j][k];
        #pragma unroll
        for (int i = 0; i < 4; i++)
            #pragma unroll
            for (int j = 0; j < 4; j++)
                acc[i][j] = fmaf(av[i], bv[j], acc[i][j]);
    }
    float b0 = b_ih[n0+tc+0], b1 = b_ih[n0+tc+1], b2 = b_ih[n0+tc+2], b3 = b_ih[n0+tc+3];
    #pragma unroll
    for (int i = 0; i < 4; i++) {
        float4 o;
        o.x = acc[i][0] + b0; o.y = acc[i][1] + b1;
        o.z = acc[i][2] + b2; o.w = acc[i][3] + b3;
        *(float4*)&g_gx[(size_t)(m0 + tr + i) * G3 + n0 + tc] = o;
    }
}

// ------------------------------------------------------------------
// K2: GRU recurrence, cluster of 4 CTAs (K split), w_hh in REGISTERS.
// CTA rank owns K-slice [64r, 64r+64) AND the same hidden-index slice,
// so hidden never crosses CTAs; only 768x4 partial sums do (DSMEM).
// 32 clusters x 4 batches each = all 128 batches, 128 CTAs = 1 wave.
// ------------------------------------------------------------------
__global__ __launch_bounds__(G3, 1) __cluster_dims__(CL, 1, 1)
void k_gru(const float* __restrict__ hidden,
           const float* __restrict__ w_hh,
           const float* __restrict__ b_hh,
           float* __restrict__ hT)
{
    __shared__ float4 hs4[NBAT][KS/4];          // local hidden slice, 4 x 64
    __shared__ float pbuf[2][CL][NBAT][192];    // partial sums, double-buffered
    int tid = threadIdx.x;
    unsigned rank;
    asm("mov.u32 %0, %%cluster_ctarank;" : "=r"(rank));
    int b0 = (blockIdx.x / CL) * NBAT;

    // weight slice into registers: row = tid, k in [KS*rank, KS*(rank+1))
    float4 w[KS/4];
    {
        const float4* wsrc = (const float4*)(w_hh + (size_t)tid * HD + KS * rank);
        #pragma unroll
        for (int i = 0; i < KS/4; i++) w[i] = wsrc[i];
    }

    float* hs = (float*)hs4;
    int gb = tid >> 6, gj = tid & 63;           // gate-thread coords (tid<256)
    int hidx = KS * (int)rank + gj;
    float bh_r = 0.f, bh_z = 0.f, bh_n = 0.f;
    if (tid < NBAT * KS) {
        hs[gb * KS + gj] = hidden[(size_t)(b0 + gb) * HD + hidx];
        bh_r = b_hh[hidx]; bh_z = b_hh[HD + hidx]; bh_n = b_hh[2*HD + hidx];
    }

    // partial routing: row r=tid -> gate g=r>>8, dest CTA=(r&255)>>6, slot
    int dest = (tid & 255) >> 6;
    int slot = (tid >> 8) * 64 + (tid & 63);
    unsigned raddr0, raddr1;
    {
        unsigned la0 = (unsigned)__cvta_generic_to_shared(&pbuf[0][rank][0][slot]);
        unsigned la1 = (unsigned)__cvta_generic_to_shared(&pbuf[1][rank][0][slot]);
        asm("mapa.shared::cluster.u32 %0, %1, %2;" : "=r"(raddr0) : "r"(la0), "r"(dest));
        asm("mapa.shared::cluster.u32 %0, %1, %2;" : "=r"(raddr1) : "r"(la1), "r"(dest));
    }
    __syncthreads();

    for (int t = 0; t < TT; t++) {
        // prefetch gx (long-scoreboard covered by FMA block below)
        float xr = 0.f, xz = 0.f, xn = 0.f;
        if (tid < NBAT * KS) {
            const float* gxp = g_gx + ((size_t)(b0 + gb) * TT + t) * G3;
            xr = gxp[hidx]; xz = gxp[HD + hidx]; xn = gxp[2*HD + hidx];
        }
        // partial gh for 4 batches over local K slice (w in regs, h broadcast LDS)
        float a0 = 0.f, a1 = 0.f, a2 = 0.f, a3 = 0.f;
        #pragma unroll
        for (int k = 0; k < KS/4; k++) {
            float4 wv = w[k];
            float4 h0 = hs4[0][k];
            a0 = fmaf(wv.x,h0.x,a0); a0 = fmaf(wv.y,h0.y,a0);
            a0 = fmaf(wv.z,h0.z,a0); a0 = fmaf(wv.w,h0.w,a0);
            float4 h1 = hs4[1][k];
            a1 = fmaf(wv.x,h1.x,a1); a1 = fmaf(wv.y,h1.y,a1);
            a1 = fmaf(wv.z,h1.z,a1); a1 = fmaf(wv.w,h1.w,a1);
            float4 h2 = hs4[2][k];
            a2 = fmaf(wv.x,h2.x,a2); a2 = fmaf(wv.y,h2.y,a2);
            a2 = fmaf(wv.z,h2.z,a2); a2 = fmaf(wv.w,h2.w,a2);
            float4 h3 = hs4[3][k];
            a3 = fmaf(wv.x,h3.x,a3); a3 = fmaf(wv.y,h3.y,a3);
            a3 = fmaf(wv.z,h3.z,a3); a3 = fmaf(wv.w,h3.w,a3);
        }
        // ship partials to owning CTA (batch stride = 192 floats = 768 B)
        unsigned ra = (t & 1) ? raddr1 : raddr0;
        asm volatile("st.shared::cluster.f32 [%0], %1;" :: "r"(ra),         "f"(a0));
        asm volatile("st.shared::cluster.f32 [%0], %1;" :: "r"(ra + 768u),  "f"(a1));
        asm volatile("st.shared::cluster.f32 [%0], %1;" :: "r"(ra + 1536u), "f"(a2));
        asm volatile("st.shared::cluster.f32 [%0], %1;" :: "r"(ra + 2304u), "f"(a3));
        asm volatile("barrier.cluster.arrive.aligned;" ::: "memory");
        asm volatile("barrier.cluster.wait.aligned;"   ::: "memory");
        // gate phase: combine 4 partials per gate, update local h slice
        if (tid < NBAT * KS) {
            int buf = t & 1;
            float hr = pbuf[buf][0][gb][gj]      + pbuf[buf][1][gb][gj]
                     + pbuf[buf][2][gb][gj]      + pbuf[buf][3][gb][gj]      + bh_r;
            float hz = pbuf[buf][0][gb][64+gj]   + pbuf[buf][1][gb][64+gj]
                     + pbuf[buf][2][gb][64+gj]   + pbuf[buf][3][gb][64+gj]   + bh_z;
            float hn = pbuf[buf][0][gb][128+gj]  + pbuf[buf][1][gb][128+gj]
                     + pbuf[buf][2][gb][128+gj]  + pbuf[buf][3][gb][128+gj]  + bh_n;
            float r = sigm(xr + hr);
            float z = sigm(xz + hz);
            float n = tanhf(xn + r * hn);
            float hp = hs[gb*KS + gj];
            float hnew = (1.0f - z) * n + z * hp;
            hs[gb*KS + gj] = hnew;
            g_rnn[((size_t)(b0 + gb) * TT + t) * HD + hidx] = hnew;
        }
        __syncthreads();
    }
    if (tid < NBAT * KS) hT[(size_t)(b0 + gb) * HD + hidx] = hs[gb*KS + gj];
}

// ------------------------------------------------------------------
// K3a: task_enc[bt,l] = rnn[bt,:] . w_lat[l,:] + b_lat[l]
// ------------------------------------------------------------------
__global__ __launch_bounds__(256) void k_te(const float* __restrict__ w_lat,
                                            const float* __restrict__ b_lat)
{
    __shared__ float4 rows4[32 * 64];
    int tid = threadIdx.x;
    int bt0 = blockIdx.x * 32;
    const float4* rnn4 = (const float4*)g_rnn;
    for (int q = tid; q < 2048; q += 256) rows4[q] = rnn4[(size_t)bt0 * 64 + q];
    __syncthreads();
    int pair = tid >> 3;
    int l0 = (tid & 7) * 4;
    const float4* wl4 = (const float4*)w_lat;
    float acc[4];
    #pragma unroll
    for (int j = 0; j < 4; j++) acc[j] = b_lat[l0 + j];
    #pragma unroll 8
    for (int k4 = 0; k4 < 64; k4++) {
        float4 r = rows4[pair * 64 + k4];
        #pragma unroll
        for (int j = 0; j < 4; j++) {
            float4 w = wl4[(size_t)(l0 + j) * 64 + k4];
            acc[j] = fmaf(r.x, w.x, acc[j]);
            acc[j] = fmaf(r.y, w.y, acc[j]);
            acc[j] = fmaf(r.z, w.z, acc[j]);
            acc[j] = fmaf(r.w, w.w, acc[j]);
        }
    }
    float4 o = {acc[0], acc[1], acc[2], acc[3]};
    *(float4*)&g_te[(size_t)(bt0 + pair) * LD + l0] = o;
}

// ------------------------------------------------------------------
// K3b: fused params GEMM (K=32) + hyper-MLP + outputs. 8 pairs/block.
// w_par streamed as float4 (no per-thread reg cache -> no spills).
// ------------------------------------------------------------------
#define PAIRS 8
__global__ __launch_bounds__(256) void k_tail(const float* __restrict__ x,
                                              const float* __restrict__ w_par,
                                              const float* __restrict__ b_par,
                                              float* __restrict__ out_mean,
                                              float* __restrict__ out_std)
{
    __shared__ float4 te4[PAIRS][8];
    __shared__ float st_s[PAIRS][49];
    __shared__ float ps[PAIRS * NPARD];
    __shared__ float hid[PAIRS][17];
    int tid = threadIdx.x;
    int bt0 = blockIdx.x * PAIRS;

    if (tid < PAIRS * 8) {
        int p = tid >> 3, q = tid & 7;
        te4[p][q] = ((const float4*)g_te)[(size_t)(bt0 + p) * 8 + q];
    }
    for (int q = tid; q < PAIRS * 48; q += 256) {
        int p = q / 48, i = q % 48;
        st_s[p][i] = x[(size_t)(bt0 + p) * IND + i];
    }
    __syncthreads();

    // params[pair][idx] = b_par[idx] + sum_l w_par[idx][l]*te[pair][l]
    for (int idx = tid; idx < NPARD; idx += 256) {
        const float4* wp4 = (const float4*)w_par + (size_t)idx * 8;
        float bp = b_par[idx];
        float accs[PAIRS];
        #pragma unroll
        for (int p = 0; p < PAIRS; p++) accs[p] = bp;
        #pragma unroll
        for (int q = 0; q < 8; q++) {
            float4 wv = wp4[q];
            #pragma unroll
            for (int p = 0; p < PAIRS; p++) {
                float4 tv = te4[p][q];
                accs[p] = fmaf(wv.x, tv.x, accs[p]);
                accs[p] = fmaf(wv.y, tv.y, accs[p]);
                accs[p] = fmaf(wv.z, tv.z, accs[p]);
                accs[p] = fmaf(wv.w, tv.w, accs[p]);
            }
        }
        #pragma unroll
        for (int p = 0; p < PAIRS; p++) ps[p * NPARD + idx] = accs[p];
    }
    __syncthreads();

    // out_hidden[pair][p] = tanh( sum_i w_h[p][i]*state[i] + b_h[p] )
    if (tid < PAIRS * 16) {
        int pair = tid >> 4, p = tid & 15;
        const float* pp = ps + pair * NPARD;
        float a = pp[768 + p];
        #pragma unroll
        for (int i = 0; i < 48; i++) a = fmaf(pp[p * 48 + i], st_s[pair][i], a);
        hid[pair][p] = tanhf(a);
    }
    __syncthreads();

    // mlp[pair][o] = sum_p w_o[o][p]*hidden[p] + b_o[o]; mean / exp(std)
    if (tid < PAIRS * 16) {
        int pair = tid >> 4, o = tid & 15;
        const float* pp = ps + pair * NPARD;
        float m = pp[1040 + o];
        #pragma unroll
        for (int p = 0; p < 16; p++) m = fmaf(pp[784 + o * 16 + p], hid[pair][p], m);
        size_t bt = bt0 + pair;
        if (o < 8) out_mean[bt * ODD + o] = m;
        else       out_std[bt * ODD + (o - 8)] = expf(m);
    }
}

// ------------------------------------------------------------------
extern "C" void kernel_launch(void* const* d_in, const int* in_sizes, int n_in,
                              void* d_out, int out_size)
{
    const float* x      = (const float*)d_in[0];
    const float* hidden = (const float*)d_in[1];
    const float* w_ih   = (const float*)d_in[2];
    const float* w_hh   = (const float*)d_in[3];
    const float* b_ih   = (const float*)d_in[4];
    const float* b_hh   = (const float*)d_in[5];
    const float* w_lat  = (const float*)d_in[6];
    const float* b_lat  = (const float*)d_in[7];
    const float* w_par  = (const float*)d_in[8];
    const float* b_par  = (const float*)d_in[9];
    (void)in_sizes; (void)n_in; (void)out_size;

    float* out      = (float*)d_out;
    float* out_mean = out;                                  // B*T*8
    float* out_std  = out + (size_t)BB * TT * ODD;          // B*T*8
    float* out_hT   = out + (size_t)2 * BB * TT * ODD;      // B*256

    dim3 g1(G3 / 64, (BB * TT) / 64), b1(16, 16);
    k_gx  <<<g1, b1>>>(x, w_ih, b_ih);
    k_gru <<<(BB / NBAT) * CL, G3>>>(hidden, w_hh, b_hh, out_hT);
    k_te  <<<(BB * TT) / 32, 256>>>(w_lat, b_lat);
    k_tail<<<(BB * TT) / PAIRS, 256>>>(x, w_par, b_par, out_mean, out_std);
}